// round 2
// baseline (speedup 1.0000x reference)
#include <cuda_runtime.h>
#include <cuda_bf16.h>
#include <math.h>

#define NN 50000
#define EE 800000
#define INF_ 256
#define HH 4
#define FF 64
#define NH (NN*HH)        // 200000
#define EH (EE*HH)        // 3200000
#define SLOPE 0.2f

// ---------------- scratch (static device globals; no allocation) ------------
__device__ float g_h [NN*HH*FF];
__device__ float g_x1[NN*HH*FF];
__device__ float g_x2[NN*HH*FF];
__device__ float g_x3[NN*HH*FF];
__device__ float g_el[NH], g_er[NH], g_al[NH];
__device__ float g_mx_src[NH], g_mx_dst[NH];
__device__ float g_sum_src[NH], g_sum_dst[NH];
__device__ float g_e[EH];      // leaky_relu(el[src]+er[dst])
__device__ float g_c[EH];      // final per-edge coefficient (a * norm_out[src])
__device__ int   g_indeg[NN], g_outdeg[NN], g_cnt[NN];
__device__ int   g_off[NN+1];
__device__ int   g_csr_src[EE];
__device__ int   g_csr_eid[EE];
__device__ float g_nin[NN], g_nout[NN];

// ---------------- helpers ---------------------------------------------------
__device__ __forceinline__ float leaky(float x) { return x > 0.f ? x : SLOPE * x; }

__device__ __forceinline__ float warpAllReduce(float v) {
#pragma unroll
    for (int o = 16; o; o >>= 1) v += __shfl_xor_sync(0xffffffffu, v, o);
    return v;
}

__device__ __forceinline__ void atomicMaxFloat(float* addr, float val) {
    if (val >= 0.f) atomicMax((int*)addr, __float_as_int(val));
    else            atomicMin((unsigned int*)addr, __float_as_uint(val));
}

// ---------------- kernels ---------------------------------------------------
__global__ void init_kernel() {
    int i = blockIdx.x * blockDim.x + threadIdx.x;
    if (i < NN) { g_indeg[i] = 0; g_outdeg[i] = 0; g_cnt[i] = 0; }
    if (i < NH) {
        g_sum_src[i] = 0.f; g_sum_dst[i] = 0.f;
        float ninf = __int_as_float(0xff800000);
        g_mx_src[i] = ninf; g_mx_dst[i] = ninf;
    }
}

// h = feat @ W   (50000x256 @ 256x256)
__global__ void gemm_kernel(const float* __restrict__ feat,
                            const float* __restrict__ W) {
    __shared__ float sf[16][INF_ + 1];
    int row0 = blockIdx.x * 16;
    int tid  = threadIdx.x;          // 256
    for (int i = tid; i < 16 * INF_; i += 256) {
        int r = i >> 8, k = i & 255;
        sf[r][k] = feat[(row0 + r) * INF_ + k];
    }
    __syncthreads();
    float acc[16];
#pragma unroll
    for (int r = 0; r < 16; r++) acc[r] = 0.f;
    int col = tid;
    for (int k = 0; k < INF_; k++) {
        float w = W[k * 256 + col];
#pragma unroll
        for (int r = 0; r < 16; r++) acc[r] += sf[r][k] * w;
    }
#pragma unroll
    for (int r = 0; r < 16; r++) g_h[(row0 + r) * 256 + col] = acc[r];
}

// per (node,head): el, er, a_l dot products. one warp per pair.
__global__ void dots_kernel(const float* __restrict__ attn_l,
                            const float* __restrict__ attn_r,
                            const float* __restrict__ hop_attn_l) {
    int pair = blockIdx.x * 8 + (threadIdx.x >> 5);
    if (pair >= NH) return;
    int lane = threadIdx.x & 31;
    int hd = pair & 3;
    const float2* hv = (const float2*)(g_h + pair * FF);
    float2 v = hv[lane];
    const float2* al = (const float2*)(attn_l + hd * FF);
    const float2* ar = (const float2*)(attn_r + hd * FF);
    const float2* hl = (const float2*)(hop_attn_l + hd * FF);
    float2 wl = al[lane], wr = ar[lane], wh = hl[lane];
    float dl = warpAllReduce(v.x * wl.x + v.y * wl.y);
    float dr = warpAllReduce(v.x * wr.x + v.y * wr.y);
    float dh = warpAllReduce(v.x * wh.x + v.y * wh.y);
    if (lane == 0) { g_el[pair] = dl; g_er[pair] = dr; g_al[pair] = dh; }
}

// edge pass A: logits + segment max + degrees
__global__ void edgeA_kernel(const int* __restrict__ src, const int* __restrict__ dst) {
    int t = blockIdx.x * blockDim.x + threadIdx.x;
    if (t >= EH) return;
    int e = t >> 2, hd = t & 3;
    int s = src[e], d = dst[e];
    float ev = leaky(g_el[s * HH + hd] + g_er[d * HH + hd]);
    g_e[t] = ev;
    atomicMaxFloat(&g_mx_src[s * HH + hd], ev);
    atomicMaxFloat(&g_mx_dst[d * HH + hd], ev);
    if (hd == 0) { atomicAdd(&g_outdeg[s], 1); atomicAdd(&g_indeg[d], 1); }
}

__global__ void norm_kernel() {
    int i = blockIdx.x * blockDim.x + threadIdx.x;
    if (i >= NN) return;
    float od = (float)max(g_outdeg[i], 1);
    float id = (float)max(g_indeg[i], 1);
    g_nout[i] = rsqrtf(od);
    g_nin[i]  = sqrtf(id);
}

// exclusive scan of indeg -> off (single block)
__global__ void scan_kernel() {
    __shared__ int s[1024];
    __shared__ int carry_s;
    int tid = threadIdx.x;
    if (tid == 0) carry_s = 0;
    __syncthreads();
    for (int base = 0; base < NN; base += 1024) {
        int idx = base + tid;
        int v = (idx < NN) ? g_indeg[idx] : 0;
        s[tid] = v;
        __syncthreads();
        for (int off = 1; off < 1024; off <<= 1) {
            int t = (tid >= off) ? s[tid - off] : 0;
            __syncthreads();
            s[tid] += t;
            __syncthreads();
        }
        if (idx < NN) g_off[idx] = carry_s + s[tid] - v;
        __syncthreads();
        if (tid == 0) carry_s += s[1023];
        __syncthreads();
    }
    if (tid == 0) g_off[NN] = EE;
}

__global__ void scatter_kernel(const int* __restrict__ src, const int* __restrict__ dst) {
    int e = blockIdx.x * blockDim.x + threadIdx.x;
    if (e >= EE) return;
    int d = dst[e];
    int pos = g_off[d] + atomicAdd(&g_cnt[d], 1);
    g_csr_src[pos] = src[e];
    g_csr_eid[pos] = e;
}

// edge pass B: exp + segment sums
__global__ void edgeB_kernel(const int* __restrict__ src, const int* __restrict__ dst) {
    int t = blockIdx.x * blockDim.x + threadIdx.x;
    if (t >= EH) return;
    int e = t >> 2, hd = t & 3;
    int s = src[e], d = dst[e];
    float ev = g_e[t];
    float exs = __expf(ev - g_mx_src[s * HH + hd]);
    float exd = __expf(ev - g_mx_dst[d * HH + hd]);
    atomicAdd(&g_sum_src[s * HH + hd], exs);
    atomicAdd(&g_sum_dst[d * HH + hd], exd);
}

// edge pass C: final coefficient c = (a_dst^sig * a_src^(1-sig)) * norm_out[src]
__global__ void edgeC_kernel(const int* __restrict__ src, const int* __restrict__ dst,
                             const float* __restrict__ sigma) {
    int t = blockIdx.x * blockDim.x + threadIdx.x;
    if (t >= EH) return;
    float sg = 1.f / (1.f + expf(-sigma[0]));
    int e = t >> 2, hd = t & 3;
    int s = src[e], d = dst[e];
    float ev = g_e[t];
    float as = __expf(ev - g_mx_src[s * HH + hd]) / g_sum_src[s * HH + hd];
    float ad = __expf(ev - g_mx_dst[d * HH + hd]) / g_sum_dst[d * HH + hd];
    as = fmaxf(as, 1e-10f);
    ad = fmaxf(ad, 1e-10f);
    float a = expf(sg * logf(ad) + (1.f - sg) * logf(as));
    g_c[t] = a * g_nout[s];
}

// one hop: xn[d,h,:] = nin[d] * sum_{e in in(d)} c[e,h] * x[src_e,h,:]
// hop selects buffers on-device (passing __device__ symbols from host is
// invalid — it binds the host shadow object, which GB300's ATS silently
// dereferences as host memory).
__global__ void prop_kernel(int hop) {
    const float* x;
    float* xn;
    if (hop == 0)      { x = g_h;  xn = g_x1; }
    else if (hop == 1) { x = g_x1; xn = g_x2; }
    else               { x = g_x2; xn = g_x3; }
    int pair = blockIdx.x * 8 + (threadIdx.x >> 5);
    if (pair >= NH) return;
    int lane = threadIdx.x & 31;
    int n = pair >> 2, hd = pair & 3;
    int beg = g_off[n], end = g_off[n + 1];
    float ax = 0.f, ay = 0.f;
    for (int p = beg; p < end; p++) {
        int s = g_csr_src[p];
        float cw = g_c[g_csr_eid[p] * HH + hd];
        float2 v = ((const float2*)(x + (s * HH + hd) * FF))[lane];
        ax += cw * v.x;
        ay += cw * v.y;
    }
    float ni = g_nin[n];
    float2* o = (float2*)(xn + pair * FF);
    o[lane] = make_float2(ax * ni, ay * ni);
}

// hop-attention combine -> output
__global__ void combine_kernel(const float* __restrict__ hop_attn_r,
                               float* __restrict__ out) {
    int pair = blockIdx.x * 8 + (threadIdx.x >> 5);
    if (pair >= NH) return;
    int lane = threadIdx.x & 31;
    int hd = pair & 3;
    float2 wr = ((const float2*)(hop_attn_r + hd * FF))[lane];
    float2 v0 = ((const float2*)(g_h  + pair * FF))[lane];
    float2 v1 = ((const float2*)(g_x1 + pair * FF))[lane];
    float2 v2 = ((const float2*)(g_x2 + pair * FF))[lane];
    float2 v3 = ((const float2*)(g_x3 + pair * FF))[lane];
    float d0 = warpAllReduce(v0.x * wr.x + v0.y * wr.y);
    float d1 = warpAllReduce(v1.x * wr.x + v1.y * wr.y);
    float d2 = warpAllReduce(v2.x * wr.x + v2.y * wr.y);
    float d3 = warpAllReduce(v3.x * wr.x + v3.y * wr.y);
    float al = g_al[pair];
    float b0 = leaky(al + d0), b1 = leaky(al + d1);
    float b2 = leaky(al + d2), b3 = leaky(al + d3);
    float m = fmaxf(fmaxf(b0, b1), fmaxf(b2, b3));
    float e0 = expf(b0 - m), e1 = expf(b1 - m), e2 = expf(b2 - m), e3 = expf(b3 - m);
    float inv = 1.f / (e0 + e1 + e2 + e3);
    e0 *= inv; e1 *= inv; e2 *= inv; e3 *= inv;
    float2 r;
    r.x = v0.x * e0 + v1.x * e1 + v2.x * e2 + v3.x * e3;
    r.y = v0.y * e0 + v1.y * e1 + v2.y * e2 + v3.y * e3;
    ((float2*)(out + pair * FF))[lane] = r;
}

// ---------------- launch ----------------------------------------------------
extern "C" void kernel_launch(void* const* d_in, const int* in_sizes, int n_in,
                              void* d_out, int out_size) {
    const float* feat  = (const float*)d_in[0];
    const int*   src   = (const int*)d_in[1];
    const int*   dst   = (const int*)d_in[2];
    const float* W     = (const float*)d_in[3];
    const float* attn_l     = (const float*)d_in[4];
    const float* attn_r     = (const float*)d_in[5];
    const float* hop_attn_l = (const float*)d_in[6];
    const float* hop_attn_r = (const float*)d_in[7];
    const float* sigma      = (const float*)d_in[8];
    float* out = (float*)d_out;

    init_kernel<<<(NH + 255) / 256, 256>>>();
    gemm_kernel<<<NN / 16, 256>>>(feat, W);
    dots_kernel<<<(NH + 7) / 8, 256>>>(attn_l, attn_r, hop_attn_l);
    edgeA_kernel<<<(EH + 255) / 256, 256>>>(src, dst);
    norm_kernel<<<(NN + 255) / 256, 256>>>();
    scan_kernel<<<1, 1024>>>();
    scatter_kernel<<<(EE + 255) / 256, 256>>>(src, dst);
    edgeB_kernel<<<(EH + 255) / 256, 256>>>(src, dst);
    edgeC_kernel<<<(EH + 255) / 256, 256>>>(src, dst, sigma);
    prop_kernel<<<(NH + 7) / 8, 256>>>(0);
    prop_kernel<<<(NH + 7) / 8, 256>>>(1);
    prop_kernel<<<(NH + 7) / 8, 256>>>(2);
    combine_kernel<<<(NH + 7) / 8, 256>>>(hop_attn_r, out);
}

// round 3
// speedup vs baseline: 1.4950x; 1.4950x over previous
#include <cuda_runtime.h>
#include <cuda_bf16.h>
#include <math.h>

#define NN 50000
#define EE 800000
#define INF_ 256
#define HH 4
#define FF 64
#define NH (NN*HH)        // 200000
#define EH (EE*HH)        // 3200000
#define SLOPE 0.2f
#define LCLIP (-23.0258509f)   // log(1e-10)

// ---------------- scratch (static device globals; no allocation) ------------
__device__ float g_h [NN*HH*FF];
__device__ float g_x1[NN*HH*FF];
__device__ float g_x2[NN*HH*FF];
__device__ float g_x3[NN*HH*FF];
__device__ float g_el[NH], g_er[NH], g_al[NH];
__device__ float g_sum_src[NH], g_sum_dst[NH];   // exp-sums, then logs in-place
__device__ float g_e[EH];      // leaky_relu(el[src]+er[dst])
__device__ float g_c[EE*HH];   // per-edge coefficient, CSR order: [pos][hd]
__device__ int   g_indeg[NN], g_outdeg[NN], g_cnt[NN];
__device__ int   g_off[NN+1];
__device__ int   g_csr_src[EE];
__device__ int   g_pos[EE];    // edge -> CSR slot
__device__ float g_nin[NN], g_nout[NN];
__device__ int   g_bsum[256], g_boff[256];

// ---------------- helpers ---------------------------------------------------
__device__ __forceinline__ float leaky(float x) { return x > 0.f ? x : SLOPE * x; }

__device__ __forceinline__ float warpAllReduce(float v) {
#pragma unroll
    for (int o = 16; o; o >>= 1) v += __shfl_xor_sync(0xffffffffu, v, o);
    return v;
}

// ---------------- kernels ---------------------------------------------------
__global__ void init_kernel() {
    int i = blockIdx.x * blockDim.x + threadIdx.x;
    if (i < NN) { g_indeg[i] = 0; g_outdeg[i] = 0; g_cnt[i] = 0; }
    if (i < NH) { g_sum_src[i] = 0.f; g_sum_dst[i] = 0.f; }
}

// h = feat @ W   (50000x256 @ 256x256), 128x64 tile, 8x4 per thread
__global__ void gemm_kernel(const float* __restrict__ feat,
                            const float* __restrict__ W) {
    __shared__ float As[16][128];   // [k][row] transposed
    __shared__ float Bs[16][64];    // [k][col]
    int t = threadIdx.x;            // 256
    int row0 = blockIdx.x * 128;
    int col0 = blockIdx.y * 64;
    int tx = t & 15;                // 16 col-groups * 4 cols
    int ty = t >> 4;                // 16 row-groups * 8 rows
    float acc[8][4];
#pragma unroll
    for (int i = 0; i < 8; i++)
#pragma unroll
        for (int j = 0; j < 4; j++) acc[i][j] = 0.f;

    for (int k0 = 0; k0 < 256; k0 += 16) {
        // load A tile: 512 float4 (128 rows x 4), 2 per thread, transpose into As
#pragma unroll
        for (int u = 0; u < 2; u++) {
            int idx = t + u * 256;          // 0..511
            int r = idx >> 2, kq = idx & 3;
            int row = row0 + r;
            float4 f = (row < NN)
                ? *(const float4*)(feat + row * 256 + k0 + kq * 4)
                : make_float4(0.f, 0.f, 0.f, 0.f);
            As[kq * 4 + 0][r] = f.x;
            As[kq * 4 + 1][r] = f.y;
            As[kq * 4 + 2][r] = f.z;
            As[kq * 4 + 3][r] = f.w;
        }
        // load B tile: 256 float4 (16 k-rows x 16), 1 per thread
        {
            int kr = t >> 4, cc = (t & 15) * 4;
            *(float4*)&Bs[kr][cc] = *(const float4*)(W + (k0 + kr) * 256 + col0 + cc);
        }
        __syncthreads();
#pragma unroll
        for (int kk = 0; kk < 16; kk++) {
            float a[8];
#pragma unroll
            for (int i = 0; i < 8; i++) a[i] = As[kk][ty * 8 + i];
            float4 b = *(const float4*)&Bs[kk][tx * 4];
#pragma unroll
            for (int i = 0; i < 8; i++) {
                acc[i][0] += a[i] * b.x;
                acc[i][1] += a[i] * b.y;
                acc[i][2] += a[i] * b.z;
                acc[i][3] += a[i] * b.w;
            }
        }
        __syncthreads();
    }
#pragma unroll
    for (int i = 0; i < 8; i++) {
        int row = row0 + ty * 8 + i;
        if (row < NN) {
            float4 r4 = make_float4(acc[i][0], acc[i][1], acc[i][2], acc[i][3]);
            *(float4*)(g_h + row * 256 + col0 + tx * 4) = r4;
        }
    }
}

// per (node,head): el, er, a_l dot products. one warp per pair.
__global__ void dots_kernel(const float* __restrict__ attn_l,
                            const float* __restrict__ attn_r,
                            const float* __restrict__ hop_attn_l) {
    int pair = blockIdx.x * 8 + (threadIdx.x >> 5);
    if (pair >= NH) return;
    int lane = threadIdx.x & 31;
    int hd = pair & 3;
    float2 v = ((const float2*)(g_h + pair * FF))[lane];
    float2 wl = ((const float2*)(attn_l + hd * FF))[lane];
    float2 wr = ((const float2*)(attn_r + hd * FF))[lane];
    float2 wh = ((const float2*)(hop_attn_l + hd * FF))[lane];
    float dl = warpAllReduce(v.x * wl.x + v.y * wl.y);
    float dr = warpAllReduce(v.x * wr.x + v.y * wr.y);
    float dh = warpAllReduce(v.x * wh.x + v.y * wh.y);
    if (lane == 0) { g_el[pair] = dl; g_er[pair] = dr; g_al[pair] = dh; }
}

// fused edge pass: logits + exp + both segment sums + degrees (no max needed;
// logits are bounded ~|10| so exp cannot overflow; softmax value identical)
__global__ void edgeAB_kernel(const int* __restrict__ src, const int* __restrict__ dst) {
    int t = blockIdx.x * blockDim.x + threadIdx.x;
    if (t >= EH) return;
    int e = t >> 2, hd = t & 3;
    int s = src[e], d = dst[e];
    float ev = leaky(g_el[s * HH + hd] + g_er[d * HH + hd]);
    g_e[t] = ev;
    float ex = __expf(ev);
    atomicAdd(&g_sum_src[s * HH + hd], ex);
    atomicAdd(&g_sum_dst[d * HH + hd], ex);
    if (hd == 0) { atomicAdd(&g_outdeg[s], 1); atomicAdd(&g_indeg[d], 1); }
}

// degree norms + log of softmax denominators (in-place)
__global__ void norm_kernel() {
    int i = blockIdx.x * blockDim.x + threadIdx.x;
    if (i < NN) {
        g_nout[i] = rsqrtf((float)max(g_outdeg[i], 1));
        g_nin[i]  = sqrtf((float)max(g_indeg[i], 1));
    }
    if (i < NH) {
        g_sum_src[i] = __logf(g_sum_src[i]);
        g_sum_dst[i] = __logf(g_sum_dst[i]);
    }
}

// ---- two-level exclusive scan of indeg -> off ----
__global__ void scanA_kernel() {
    int t = threadIdx.x, lane = t & 31, wid = t >> 5;
    int idx = blockIdx.x * 256 + t;
    int v = (idx < NN) ? g_indeg[idx] : 0;
    int x = v;
#pragma unroll
    for (int o = 1; o < 32; o <<= 1) {
        int y = __shfl_up_sync(0xffffffffu, x, o);
        if (lane >= o) x += y;
    }
    __shared__ int ws[8];
    if (lane == 31) ws[wid] = x;
    __syncthreads();
    if (t < 8) {
        int y = ws[t];
#pragma unroll
        for (int o = 1; o < 8; o <<= 1) {
            int z = __shfl_up_sync(0xffu, y, o);
            if (t >= o) y += z;
        }
        ws[t] = y;
    }
    __syncthreads();
    int incl = x + (wid ? ws[wid - 1] : 0);
    if (idx < NN) g_off[idx] = incl - v;
    if (t == 255) g_bsum[blockIdx.x] = incl;
}

__global__ void scanB_kernel(int nblk) {
    int t = threadIdx.x, lane = t & 31, wid = t >> 5;
    int v = (t < nblk) ? g_bsum[t] : 0;
    int x = v;
#pragma unroll
    for (int o = 1; o < 32; o <<= 1) {
        int y = __shfl_up_sync(0xffffffffu, x, o);
        if (lane >= o) x += y;
    }
    __shared__ int ws[8];
    if (lane == 31) ws[wid] = x;
    __syncthreads();
    if (t < 8) {
        int y = ws[t];
#pragma unroll
        for (int o = 1; o < 8; o <<= 1) {
            int z = __shfl_up_sync(0xffu, y, o);
            if (t >= o) y += z;
        }
        ws[t] = y;
    }
    __syncthreads();
    int incl = x + (wid ? ws[wid - 1] : 0);
    g_boff[t] = incl - v;
}

__global__ void scanC_kernel() {
    int idx = blockIdx.x * 256 + threadIdx.x;
    if (idx < NN) g_off[idx] += g_boff[blockIdx.x];
    if (idx == 0) g_off[NN] = EE;
}

__global__ void scatter_kernel(const int* __restrict__ src, const int* __restrict__ dst) {
    int e = blockIdx.x * blockDim.x + threadIdx.x;
    if (e >= EE) return;
    int d = dst[e];
    int pos = g_off[d] + atomicAdd(&g_cnt[d], 1);
    g_csr_src[pos] = src[e];
    g_pos[e] = pos;
}

// final coefficient, written directly in CSR order:
// a = clip(a_dst)^s * clip(a_src)^(1-s);  clip in log-space == max(.,log 1e-10)
__global__ void edgeC_kernel(const int* __restrict__ src, const int* __restrict__ dst,
                             const float* __restrict__ sigma) {
    int t = blockIdx.x * blockDim.x + threadIdx.x;
    if (t >= EH) return;
    float sg = 1.f / (1.f + __expf(-sigma[0]));
    int e = t >> 2, hd = t & 3;
    int s = src[e], d = dst[e];
    float ev = g_e[t];
    float ls = fmaxf(ev - g_sum_src[s * HH + hd], LCLIP);
    float ld = fmaxf(ev - g_sum_dst[d * HH + hd], LCLIP);
    g_c[g_pos[e] * HH + hd] = __expf((1.f - sg) * ls + sg * ld) * g_nout[s];
}

// one hop: xn[d,h,:] = nin[d] * sum_{e in in(d)} c[e,h] * x[src_e,h,:]
__global__ void prop_kernel(int hop) {
    const float* x;
    float* xn;
    if (hop == 0)      { x = g_h;  xn = g_x1; }
    else if (hop == 1) { x = g_x1; xn = g_x2; }
    else               { x = g_x2; xn = g_x3; }
    int pair = blockIdx.x * 8 + (threadIdx.x >> 5);
    if (pair >= NH) return;
    int lane = threadIdx.x & 31;
    int n = pair >> 2, hd = pair & 3;
    int beg = g_off[n], end = g_off[n + 1];
    float ax = 0.f, ay = 0.f;
    int p = beg;
    for (; p + 1 < end; p += 2) {
        int s0 = g_csr_src[p];
        int s1 = g_csr_src[p + 1];
        float c0 = g_c[p * HH + hd];
        float c1 = g_c[(p + 1) * HH + hd];
        float2 v0 = ((const float2*)(x + (s0 * HH + hd) * FF))[lane];
        float2 v1 = ((const float2*)(x + (s1 * HH + hd) * FF))[lane];
        ax += c0 * v0.x + c1 * v1.x;
        ay += c0 * v0.y + c1 * v1.y;
    }
    if (p < end) {
        int s0 = g_csr_src[p];
        float c0 = g_c[p * HH + hd];
        float2 v0 = ((const float2*)(x + (s0 * HH + hd) * FF))[lane];
        ax += c0 * v0.x;
        ay += c0 * v0.y;
    }
    float ni = g_nin[n];
    ((float2*)(xn + pair * FF))[lane] = make_float2(ax * ni, ay * ni);
}

// hop-attention combine -> output
__global__ void combine_kernel(const float* __restrict__ hop_attn_r,
                               float* __restrict__ out) {
    int pair = blockIdx.x * 8 + (threadIdx.x >> 5);
    if (pair >= NH) return;
    int lane = threadIdx.x & 31;
    int hd = pair & 3;
    float2 wr = ((const float2*)(hop_attn_r + hd * FF))[lane];
    float2 v0 = ((const float2*)(g_h  + pair * FF))[lane];
    float2 v1 = ((const float2*)(g_x1 + pair * FF))[lane];
    float2 v2 = ((const float2*)(g_x2 + pair * FF))[lane];
    float2 v3 = ((const float2*)(g_x3 + pair * FF))[lane];
    float d0 = warpAllReduce(v0.x * wr.x + v0.y * wr.y);
    float d1 = warpAllReduce(v1.x * wr.x + v1.y * wr.y);
    float d2 = warpAllReduce(v2.x * wr.x + v2.y * wr.y);
    float d3 = warpAllReduce(v3.x * wr.x + v3.y * wr.y);
    float al = g_al[pair];
    float b0 = leaky(al + d0), b1 = leaky(al + d1);
    float b2 = leaky(al + d2), b3 = leaky(al + d3);
    float m = fmaxf(fmaxf(b0, b1), fmaxf(b2, b3));
    float e0 = __expf(b0 - m), e1 = __expf(b1 - m);
    float e2 = __expf(b2 - m), e3 = __expf(b3 - m);
    float inv = 1.f / (e0 + e1 + e2 + e3);
    e0 *= inv; e1 *= inv; e2 *= inv; e3 *= inv;
    float2 r;
    r.x = v0.x * e0 + v1.x * e1 + v2.x * e2 + v3.x * e3;
    r.y = v0.y * e0 + v1.y * e1 + v2.y * e2 + v3.y * e3;
    ((float2*)(out + pair * FF))[lane] = r;
}

// ---------------- launch ----------------------------------------------------
extern "C" void kernel_launch(void* const* d_in, const int* in_sizes, int n_in,
                              void* d_out, int out_size) {
    const float* feat  = (const float*)d_in[0];
    const int*   src   = (const int*)d_in[1];
    const int*   dst   = (const int*)d_in[2];
    const float* W     = (const float*)d_in[3];
    const float* attn_l     = (const float*)d_in[4];
    const float* attn_r     = (const float*)d_in[5];
    const float* hop_attn_l = (const float*)d_in[6];
    const float* hop_attn_r = (const float*)d_in[7];
    const float* sigma      = (const float*)d_in[8];
    float* out = (float*)d_out;

    const int NBLK = (NN + 255) / 256;   // 196

    init_kernel<<<(NH + 255) / 256, 256>>>();
    gemm_kernel<<<dim3((NN + 127) / 128, 4), 256>>>(feat, W);
    dots_kernel<<<(NH + 7) / 8, 256>>>(attn_l, attn_r, hop_attn_l);
    edgeAB_kernel<<<(EH + 255) / 256, 256>>>(src, dst);
    norm_kernel<<<(NH + 255) / 256, 256>>>();
    scanA_kernel<<<NBLK, 256>>>();
    scanB_kernel<<<1, 256>>>(NBLK);
    scanC_kernel<<<NBLK, 256>>>();
    scatter_kernel<<<(EE + 255) / 256, 256>>>(src, dst);
    edgeC_kernel<<<(EH + 255) / 256, 256>>>(src, dst, sigma);
    prop_kernel<<<(NH + 7) / 8, 256>>>(0);
    prop_kernel<<<(NH + 7) / 8, 256>>>(1);
    prop_kernel<<<(NH + 7) / 8, 256>>>(2);
    combine_kernel<<<(NH + 7) / 8, 256>>>(hop_attn_r, out);
}

// round 5
// speedup vs baseline: 1.6617x; 1.1115x over previous
#include <cuda_runtime.h>
#include <cuda_bf16.h>
#include <mma.h>
#include <math.h>
#include <stdint.h>

using namespace nvcuda;

#define NN 50000
#define NPAD 50048            // 391 * 128
#define EE 800000
#define INF_ 256
#define HH 4
#define FF 64
#define NH (NN*HH)            // 200000
#define EH (EE*HH)            // 3200000
#define SLOPE 0.2f
#define LCLIP (-23.0258509f)  // log(1e-10)

// ---------------- scratch (static device globals; no allocation) ------------
__device__ float g_h [NPAD*HH*FF];   // padded rows for guard-free wmma stores
__device__ float g_x1[NN*HH*FF];
__device__ float g_x2[NN*HH*FF];
__device__ float g_x3[NN*HH*FF];
__device__ float g_el[NH], g_er[NH], g_al[NH];
__device__ float g_sum_src[NH], g_sum_dst[NH];   // exp-sums, then logs in-place
__device__ float g_e[EH];      // leaky_relu(el[src]+er[dst])
__device__ float g_c[EE*HH];   // per-edge coefficient, CSR order: [pos][hd]
__device__ int   g_indeg[NN], g_outdeg[NN], g_cnt[NN];
__device__ int   g_off[NN+1];
__device__ int   g_csr_src[EE];
__device__ int   g_pos[EE];    // edge -> CSR slot
__device__ float g_nin[NN], g_nout[NN];
__device__ int   g_bsum[256], g_boff[256];
// split-bf16 operands (zero-init padding rows stay zero)
__device__ __nv_bfloat16 g_Ah[NPAD*256];
__device__ __nv_bfloat16 g_Al[NPAD*256];
__device__ __nv_bfloat16 g_Wh[256*256];   // [k][n] row-major
__device__ __nv_bfloat16 g_Wl[256*256];

// ---------------- helpers ---------------------------------------------------
__device__ __forceinline__ float leaky(float x) { return x > 0.f ? x : SLOPE * x; }

__device__ __forceinline__ float warpAllReduce(float v) {
#pragma unroll
    for (int o = 16; o; o >>= 1) v += __shfl_xor_sync(0xffffffffu, v, o);
    return v;
}

// ---------------- kernels ---------------------------------------------------
__global__ void init_kernel() {
    int i = blockIdx.x * blockDim.x + threadIdx.x;
    if (i < NN) { g_indeg[i] = 0; g_outdeg[i] = 0; g_cnt[i] = 0; }
    if (i < NH) { g_sum_src[i] = 0.f; g_sum_dst[i] = 0.f; }
}

// feat -> split bf16 hi/lo (row-major [m][k]); float4 per thread
__global__ void convertA_kernel(const float* __restrict__ feat) {
    int idx = blockIdx.x * 256 + threadIdx.x;      // NN*256/4 threads
    if (idx >= NN * 64) return;
    float4 v = ((const float4*)feat)[idx];
    __nv_bfloat16 hx = __float2bfloat16_rn(v.x), hy = __float2bfloat16_rn(v.y);
    __nv_bfloat16 hz = __float2bfloat16_rn(v.z), hw = __float2bfloat16_rn(v.w);
    __nv_bfloat162 h01(hx, hy), h23(hz, hw);
    __nv_bfloat162 l01(__float2bfloat16_rn(v.x - __bfloat162float(hx)),
                       __float2bfloat16_rn(v.y - __bfloat162float(hy)));
    __nv_bfloat162 l23(__float2bfloat16_rn(v.z - __bfloat162float(hz)),
                       __float2bfloat16_rn(v.w - __bfloat162float(hw)));
    ((__nv_bfloat162*)g_Ah)[idx * 2]     = h01;
    ((__nv_bfloat162*)g_Ah)[idx * 2 + 1] = h23;
    ((__nv_bfloat162*)g_Al)[idx * 2]     = l01;
    ((__nv_bfloat162*)g_Al)[idx * 2 + 1] = l23;
}

// W -> split bf16 hi/lo, same [k][n] layout
__global__ void convertW_kernel(const float* __restrict__ W) {
    int idx = blockIdx.x * 256 + threadIdx.x;      // 65536/4 threads
    if (idx >= 64 * 256) return;
    float4 v = ((const float4*)W)[idx];
    __nv_bfloat16 hx = __float2bfloat16_rn(v.x), hy = __float2bfloat16_rn(v.y);
    __nv_bfloat16 hz = __float2bfloat16_rn(v.z), hw = __float2bfloat16_rn(v.w);
    ((__nv_bfloat162*)g_Wh)[idx * 2]     = __nv_bfloat162(hx, hy);
    ((__nv_bfloat162*)g_Wh)[idx * 2 + 1] = __nv_bfloat162(hz, hw);
    ((__nv_bfloat162*)g_Wl)[idx * 2]     = __nv_bfloat162(
        __float2bfloat16_rn(v.x - __bfloat162float(hx)),
        __float2bfloat16_rn(v.y - __bfloat162float(hy)));
    ((__nv_bfloat162*)g_Wl)[idx * 2 + 1] = __nv_bfloat162(
        __float2bfloat16_rn(v.z - __bfloat162float(hz)),
        __float2bfloat16_rn(v.w - __bfloat162float(hw)));
}

// tensor-core GEMM via wmma (HMMA path; tcgen05 unavailable on compute_103).
// h = feat @ W with split-bf16 3-product emulation.
#define BM 128
#define BN 128
#define BK 64
#define LDA 72     // 64 + 8 pad (bf16)
#define LDB 136    // 128 + 8 pad
#define GS_AH 0
#define GS_AL (BM*LDA)
#define GS_BH (2*BM*LDA)
#define GS_BL (2*BM*LDA + BK*LDB)
#define GS_TOTAL_ELEM (2*BM*LDA + 2*BK*LDB)      // 35840 bf16 = 71680 B

__global__ void __launch_bounds__(256) gemm_wmma_kernel() {
    extern __shared__ __nv_bfloat16 sm[];
    int tid = threadIdx.x, wid = tid >> 5;
    int wy = wid & 3, wx = wid >> 2;              // 4 x 2 warp grid
    int row0 = blockIdx.x * BM, col0 = blockIdx.y * BN;

    wmma::fragment<wmma::accumulator, 16, 16, 16, float> acc[2][4];
#pragma unroll
    for (int i = 0; i < 2; i++)
#pragma unroll
        for (int j = 0; j < 4; j++) wmma::fill_fragment(acc[i][j], 0.f);

    for (int c = 0; c < 4; c++) {
        // stage A chunk: 128 x 64 hi/lo (1024 uint4 each, 4/thread)
#pragma unroll
        for (int u = 0; u < 4; u++) {
            int idx = tid + u * 256;
            int r = idx >> 3, kq = idx & 7;
            size_t g = (size_t)(row0 + r) * 256 + c * 64 + kq * 8;
            *(uint4*)(sm + GS_AH + r * LDA + kq * 8) = *(const uint4*)(g_Ah + g);
            *(uint4*)(sm + GS_AL + r * LDA + kq * 8) = *(const uint4*)(g_Al + g);
        }
        // stage B chunk: 64 x 128 hi/lo
#pragma unroll
        for (int u = 0; u < 4; u++) {
            int idx = tid + u * 256;
            int r = idx >> 4, cq = idx & 15;
            size_t g = (size_t)(c * 64 + r) * 256 + col0 + cq * 8;
            *(uint4*)(sm + GS_BH + r * LDB + cq * 8) = *(const uint4*)(g_Wh + g);
            *(uint4*)(sm + GS_BL + r * LDB + cq * 8) = *(const uint4*)(g_Wl + g);
        }
        __syncthreads();

#pragma unroll
        for (int kk = 0; kk < 4; kk++) {
            wmma::fragment<wmma::matrix_a, 16, 16, 16, __nv_bfloat16, wmma::row_major> fa_h[2], fa_l[2];
            wmma::fragment<wmma::matrix_b, 16, 16, 16, __nv_bfloat16, wmma::row_major> fb_h[4], fb_l[4];
#pragma unroll
            for (int i = 0; i < 2; i++) {
                const __nv_bfloat16* p = sm + GS_AH + (wy * 32 + i * 16) * LDA + kk * 16;
                wmma::load_matrix_sync(fa_h[i], p, LDA);
                wmma::load_matrix_sync(fa_l[i], p + (GS_AL - GS_AH), LDA);
            }
#pragma unroll
            for (int j = 0; j < 4; j++) {
                const __nv_bfloat16* p = sm + GS_BH + (kk * 16) * LDB + wx * 64 + j * 16;
                wmma::load_matrix_sync(fb_h[j], p, LDB);
                wmma::load_matrix_sync(fb_l[j], p + (GS_BL - GS_BH), LDB);
            }
#pragma unroll
            for (int i = 0; i < 2; i++)
#pragma unroll
                for (int j = 0; j < 4; j++) {
                    wmma::mma_sync(acc[i][j], fa_h[i], fb_h[j], acc[i][j]);
                    wmma::mma_sync(acc[i][j], fa_h[i], fb_l[j], acc[i][j]);
                    wmma::mma_sync(acc[i][j], fa_l[i], fb_h[j], acc[i][j]);
                }
        }
        __syncthreads();
    }
    // store 32x64 per warp (g_h is row-padded to NPAD, no guards needed)
#pragma unroll
    for (int i = 0; i < 2; i++)
#pragma unroll
        for (int j = 0; j < 4; j++) {
            float* p = g_h + (size_t)(row0 + wy * 32 + i * 16) * 256 + col0 + wx * 64 + j * 16;
            wmma::store_matrix_sync(p, acc[i][j], 256, wmma::mem_row_major);
        }
}

// per (node,head): el, er, a_l dot products. one warp per pair.
__global__ void dots_kernel(const float* __restrict__ attn_l,
                            const float* __restrict__ attn_r,
                            const float* __restrict__ hop_attn_l) {
    int pair = blockIdx.x * 8 + (threadIdx.x >> 5);
    if (pair >= NH) return;
    int lane = threadIdx.x & 31;
    int hd = pair & 3;
    float2 v = ((const float2*)(g_h + (size_t)pair * FF))[lane];
    float2 wl = ((const float2*)(attn_l + hd * FF))[lane];
    float2 wr = ((const float2*)(attn_r + hd * FF))[lane];
    float2 wh = ((const float2*)(hop_attn_l + hd * FF))[lane];
    float dl = warpAllReduce(v.x * wl.x + v.y * wl.y);
    float dr = warpAllReduce(v.x * wr.x + v.y * wr.y);
    float dh = warpAllReduce(v.x * wh.x + v.y * wh.y);
    if (lane == 0) { g_el[pair] = dl; g_er[pair] = dr; g_al[pair] = dh; }
}

// fused edge pass: logits + exp + both segment sums + degrees
__global__ void edgeAB_kernel(const int* __restrict__ src, const int* __restrict__ dst) {
    int t = blockIdx.x * blockDim.x + threadIdx.x;
    if (t >= EH) return;
    int e = t >> 2, hd = t & 3;
    int s = src[e], d = dst[e];
    float ev = leaky(g_el[s * HH + hd] + g_er[d * HH + hd]);
    g_e[t] = ev;
    float ex = __expf(ev);
    atomicAdd(&g_sum_src[s * HH + hd], ex);
    atomicAdd(&g_sum_dst[d * HH + hd], ex);
    if (hd == 0) { atomicAdd(&g_outdeg[s], 1); atomicAdd(&g_indeg[d], 1); }
}

// degree norms + log of softmax denominators (in-place)
__global__ void norm_kernel() {
    int i = blockIdx.x * blockDim.x + threadIdx.x;
    if (i < NN) {
        g_nout[i] = rsqrtf((float)max(g_outdeg[i], 1));
        g_nin[i]  = sqrtf((float)max(g_indeg[i], 1));
    }
    if (i < NH) {
        g_sum_src[i] = __logf(g_sum_src[i]);
        g_sum_dst[i] = __logf(g_sum_dst[i]);
    }
}

// ---- two-level exclusive scan of indeg -> off ----
__global__ void scanA_kernel() {
    int t = threadIdx.x, lane = t & 31, wid = t >> 5;
    int idx = blockIdx.x * 256 + t;
    int v = (idx < NN) ? g_indeg[idx] : 0;
    int x = v;
#pragma unroll
    for (int o = 1; o < 32; o <<= 1) {
        int y = __shfl_up_sync(0xffffffffu, x, o);
        if (lane >= o) x += y;
    }
    __shared__ int ws[8];
    if (lane == 31) ws[wid] = x;
    __syncthreads();
    if (t < 8) {
        int y = ws[t];
#pragma unroll
        for (int o = 1; o < 8; o <<= 1) {
            int z = __shfl_up_sync(0xffu, y, o);
            if (t >= o) y += z;
        }
        ws[t] = y;
    }
    __syncthreads();
    int incl = x + (wid ? ws[wid - 1] : 0);
    if (idx < NN) g_off[idx] = incl - v;
    if (t == 255) g_bsum[blockIdx.x] = incl;
}

__global__ void scanB_kernel(int nblk) {
    int t = threadIdx.x, lane = t & 31, wid = t >> 5;
    int v = (t < nblk) ? g_bsum[t] : 0;
    int x = v;
#pragma unroll
    for (int o = 1; o < 32; o <<= 1) {
        int y = __shfl_up_sync(0xffffffffu, x, o);
        if (lane >= o) x += y;
    }
    __shared__ int ws[8];
    if (lane == 31) ws[wid] = x;
    __syncthreads();
    if (t < 8) {
        int y = ws[t];
#pragma unroll
        for (int o = 1; o < 8; o <<= 1) {
            int z = __shfl_up_sync(0xffu, y, o);
            if (t >= o) y += z;
        }
        ws[t] = y;
    }
    __syncthreads();
    int incl = x + (wid ? ws[wid - 1] : 0);
    g_boff[t] = incl - v;
}

__global__ void scanC_kernel() {
    int idx = blockIdx.x * 256 + threadIdx.x;
    if (idx < NN) g_off[idx] += g_boff[blockIdx.x];
    if (idx == 0) g_off[NN] = EE;
}

__global__ void scatter_kernel(const int* __restrict__ src, const int* __restrict__ dst) {
    int e = blockIdx.x * blockDim.x + threadIdx.x;
    if (e >= EE) return;
    int d = dst[e];
    int pos = g_off[d] + atomicAdd(&g_cnt[d], 1);
    g_csr_src[pos] = src[e];
    g_pos[e] = pos;
}

// final coefficient, written directly in CSR order
__global__ void edgeC_kernel(const int* __restrict__ src, const int* __restrict__ dst,
                             const float* __restrict__ sigma) {
    int t = blockIdx.x * blockDim.x + threadIdx.x;
    if (t >= EH) return;
    float sg = 1.f / (1.f + __expf(-sigma[0]));
    int e = t >> 2, hd = t & 3;
    int s = src[e], d = dst[e];
    float ev = g_e[t];
    float ls = fmaxf(ev - g_sum_src[s * HH + hd], LCLIP);
    float ld = fmaxf(ev - g_sum_dst[d * HH + hd], LCLIP);
    g_c[g_pos[e] * HH + hd] = __expf((1.f - sg) * ls + sg * ld) * g_nout[s];
}

// one hop: xn[d,h,:] = nin[d] * sum_{e in in(d)} c[e,h] * x[src_e,h,:]
__global__ void prop_kernel(int hop) {
    const float* x;
    float* xn;
    if (hop == 0)      { x = g_h;  xn = g_x1; }
    else if (hop == 1) { x = g_x1; xn = g_x2; }
    else               { x = g_x2; xn = g_x3; }
    int pair = blockIdx.x * 8 + (threadIdx.x >> 5);
    if (pair >= NH) return;
    int lane = threadIdx.x & 31;
    int n = pair >> 2, hd = pair & 3;
    int beg = g_off[n], end = g_off[n + 1];
    float ax = 0.f, ay = 0.f;
    int p = beg;
    for (; p + 1 < end; p += 2) {
        int s0 = g_csr_src[p];
        int s1 = g_csr_src[p + 1];
        float c0 = g_c[p * HH + hd];
        float c1 = g_c[(p + 1) * HH + hd];
        float2 v0 = ((const float2*)(x + (size_t)(s0 * HH + hd) * FF))[lane];
        float2 v1 = ((const float2*)(x + (size_t)(s1 * HH + hd) * FF))[lane];
        ax += c0 * v0.x + c1 * v1.x;
        ay += c0 * v0.y + c1 * v1.y;
    }
    if (p < end) {
        int s0 = g_csr_src[p];
        float c0 = g_c[p * HH + hd];
        float2 v0 = ((const float2*)(x + (size_t)(s0 * HH + hd) * FF))[lane];
        ax += c0 * v0.x;
        ay += c0 * v0.y;
    }
    float ni = g_nin[n];
    ((float2*)(xn + (size_t)pair * FF))[lane] = make_float2(ax * ni, ay * ni);
}

// hop-attention combine -> output
__global__ void combine_kernel(const float* __restrict__ hop_attn_r,
                               float* __restrict__ out) {
    int pair = blockIdx.x * 8 + (threadIdx.x >> 5);
    if (pair >= NH) return;
    int lane = threadIdx.x & 31;
    int hd = pair & 3;
    float2 wr = ((const float2*)(hop_attn_r + hd * FF))[lane];
    float2 v0 = ((const float2*)(g_h  + (size_t)pair * FF))[lane];
    float2 v1 = ((const float2*)(g_x1 + (size_t)pair * FF))[lane];
    float2 v2 = ((const float2*)(g_x2 + (size_t)pair * FF))[lane];
    float2 v3 = ((const float2*)(g_x3 + (size_t)pair * FF))[lane];
    float d0 = warpAllReduce(v0.x * wr.x + v0.y * wr.y);
    float d1 = warpAllReduce(v1.x * wr.x + v1.y * wr.y);
    float d2 = warpAllReduce(v2.x * wr.x + v2.y * wr.y);
    float d3 = warpAllReduce(v3.x * wr.x + v3.y * wr.y);
    float al = g_al[pair];
    float b0 = leaky(al + d0), b1 = leaky(al + d1);
    float b2 = leaky(al + d2), b3 = leaky(al + d3);
    float m = fmaxf(fmaxf(b0, b1), fmaxf(b2, b3));
    float e0 = __expf(b0 - m), e1 = __expf(b1 - m);
    float e2 = __expf(b2 - m), e3 = __expf(b3 - m);
    float inv = 1.f / (e0 + e1 + e2 + e3);
    e0 *= inv; e1 *= inv; e2 *= inv; e3 *= inv;
    float2 r;
    r.x = v0.x * e0 + v1.x * e1 + v2.x * e2 + v3.x * e3;
    r.y = v0.y * e0 + v1.y * e1 + v2.y * e2 + v3.y * e3;
    ((float2*)(out + (size_t)pair * FF))[lane] = r;
}

// ---------------- launch ----------------------------------------------------
extern "C" void kernel_launch(void* const* d_in, const int* in_sizes, int n_in,
                              void* d_out, int out_size) {
    const float* feat  = (const float*)d_in[0];
    const int*   src   = (const int*)d_in[1];
    const int*   dst   = (const int*)d_in[2];
    const float* W     = (const float*)d_in[3];
    const float* attn_l     = (const float*)d_in[4];
    const float* attn_r     = (const float*)d_in[5];
    const float* hop_attn_l = (const float*)d_in[6];
    const float* hop_attn_r = (const float*)d_in[7];
    const float* sigma      = (const float*)d_in[8];
    float* out = (float*)d_out;

    const int NBLK = (NN + 255) / 256;   // 196
    const int GS_BYTES = GS_TOTAL_ELEM * 2;

    cudaFuncSetAttribute(gemm_wmma_kernel,
                         cudaFuncAttributeMaxDynamicSharedMemorySize, GS_BYTES);

    init_kernel<<<(NH + 255) / 256, 256>>>();
    convertA_kernel<<<(NN * 64 + 255) / 256, 256>>>(feat);
    convertW_kernel<<<64, 256>>>(W);
    gemm_wmma_kernel<<<dim3(NPAD / BM, 2), 256, GS_BYTES>>>();
    dots_kernel<<<(NH + 7) / 8, 256>>>(attn_l, attn_r, hop_attn_l);
    edgeAB_kernel<<<(EH + 255) / 256, 256>>>(src, dst);
    norm_kernel<<<(NH + 255) / 256, 256>>>();
    scanA_kernel<<<NBLK, 256>>>();
    scanB_kernel<<<1, 256>>>(NBLK);
    scanC_kernel<<<NBLK, 256>>>();
    scatter_kernel<<<(EE + 255) / 256, 256>>>(src, dst);
    edgeC_kernel<<<(EH + 255) / 256, 256>>>(src, dst, sigma);
    prop_kernel<<<(NH + 7) / 8, 256>>>(0);
    prop_kernel<<<(NH + 7) / 8, 256>>>(1);
    prop_kernel<<<(NH + 7) / 8, 256>>>(2);
    combine_kernel<<<(NH + 7) / 8, 256>>>(hop_attn_r, out);
}

// round 6
// speedup vs baseline: 1.7607x; 1.0596x over previous
#include <cuda_runtime.h>
#include <cuda_bf16.h>
#include <mma.h>
#include <math.h>
#include <stdint.h>

using namespace nvcuda;

#define NN 50000
#define NPAD 50048            // 391 * 128
#define EE 800000
#define INF_ 256
#define HH 4
#define FF 64
#define NH (NN*HH)            // 200000
#define EH (EE*HH)            // 3200000
#define SLOPE 0.2f
#define LCLIP (-23.0258509f)  // log(1e-10)

// ---------------- scratch (static device globals; no allocation) ------------
__device__ float g_h [NPAD*HH*FF];   // padded rows for guard-free wmma stores
__device__ float g_x1[NN*HH*FF];
__device__ float g_x2[NN*HH*FF];
__device__ float g_x3[NN*HH*FF];
__device__ float g_el[NH], g_er[NH], g_al[NH];
__device__ float g_sum_src[NH], g_sum_dst[NH];   // exp-sums, then logs in-place
__device__ float g_e[EH];      // leaky_relu(el[src]+er[dst])
__device__ float g_c[EE*HH];   // per-edge coefficient, CSR order: [pos][hd]
__device__ int   g_indeg[NN], g_outdeg[NN], g_cnt[NN];
__device__ int   g_off[NN+1];
__device__ int   g_csr_src[EE];
__device__ int   g_pos[EE];    // edge -> CSR slot
__device__ float g_nin[NN], g_nout[NN];
__device__ int   g_bsum[256], g_boff[256];
__device__ __nv_bfloat16 g_Wh[256*256];   // [k][n] row-major, split hi/lo
__device__ __nv_bfloat16 g_Wl[256*256];

// ---------------- helpers ---------------------------------------------------
__device__ __forceinline__ float leaky(float x) { return x > 0.f ? x : SLOPE * x; }

__device__ __forceinline__ float warpAllReduce(float v) {
#pragma unroll
    for (int o = 16; o; o >>= 1) v += __shfl_xor_sync(0xffffffffu, v, o);
    return v;
}

// ---------------- kernels ---------------------------------------------------
__global__ void init_kernel() {
    int i = blockIdx.x * blockDim.x + threadIdx.x;
    if (i < NN) { g_indeg[i] = 0; g_outdeg[i] = 0; g_cnt[i] = 0; }
    if (i < NH) { g_sum_src[i] = 0.f; g_sum_dst[i] = 0.f; }
}

// W -> split bf16 hi/lo, same [k][n] layout
__global__ void convertW_kernel(const float* __restrict__ W) {
    int idx = blockIdx.x * 256 + threadIdx.x;      // 65536/4 threads
    if (idx >= 64 * 256) return;
    float4 v = ((const float4*)W)[idx];
    __nv_bfloat16 hx = __float2bfloat16_rn(v.x), hy = __float2bfloat16_rn(v.y);
    __nv_bfloat16 hz = __float2bfloat16_rn(v.z), hw = __float2bfloat16_rn(v.w);
    ((__nv_bfloat162*)g_Wh)[idx * 2]     = __nv_bfloat162(hx, hy);
    ((__nv_bfloat162*)g_Wh)[idx * 2 + 1] = __nv_bfloat162(hz, hw);
    ((__nv_bfloat162*)g_Wl)[idx * 2]     = __nv_bfloat162(
        __float2bfloat16_rn(v.x - __bfloat162float(hx)),
        __float2bfloat16_rn(v.y - __bfloat162float(hy)));
    ((__nv_bfloat162*)g_Wl)[idx * 2 + 1] = __nv_bfloat162(
        __float2bfloat16_rn(v.z - __bfloat162float(hz)),
        __float2bfloat16_rn(v.w - __bfloat162float(hw)));
}

// tensor-core GEMM via wmma, split-bf16 3-product emulation, inline A convert,
// double-buffered smem with register prefetch.
#define BM 128
#define BN 128
#define BK 64
#define LDA 72     // 64 + 8 pad (bf16)
#define LDB 136    // 128 + 8 pad
#define CH_AH 0
#define CH_AL (BM*LDA)
#define CH_BH (2*BM*LDA)
#define CH_BL (2*BM*LDA + BK*LDB)
#define CH_ELEM (2*BM*LDA + 2*BK*LDB)            // 35840 bf16 per buffer
#define GS_BYTES (2*CH_ELEM*2)                   // 143360 B

struct Pref {
    float4 a[8];
    uint4  bh[4], bl[4];
};

__device__ __forceinline__ void gemm_load(Pref& P, const float* __restrict__ feat,
                                          int row0, int col0, int c, int tid) {
#pragma unroll
    for (int u = 0; u < 8; u++) {
        int idx = tid + u * 256;                  // 0..2047
        int r = idx >> 4, kq = idx & 15;
        int row = row0 + r;
        P.a[u] = (row < NN)
            ? *(const float4*)(feat + (size_t)row * 256 + c * 64 + kq * 4)
            : make_float4(0.f, 0.f, 0.f, 0.f);
    }
#pragma unroll
    for (int u = 0; u < 4; u++) {
        int idx = tid + u * 256;                  // 0..1023
        int r = idx >> 4, cq = idx & 15;
        size_t g = (size_t)(c * 64 + r) * 256 + col0 + cq * 8;
        P.bh[u] = *(const uint4*)(g_Wh + g);
        P.bl[u] = *(const uint4*)(g_Wl + g);
    }
}

__device__ __forceinline__ void gemm_store(const Pref& P, __nv_bfloat16* buf, int tid) {
#pragma unroll
    for (int u = 0; u < 8; u++) {
        int idx = tid + u * 256;
        int r = idx >> 4, kq = idx & 15;
        float4 v = P.a[u];
        __nv_bfloat16 hx = __float2bfloat16_rn(v.x), hy = __float2bfloat16_rn(v.y);
        __nv_bfloat16 hz = __float2bfloat16_rn(v.z), hw = __float2bfloat16_rn(v.w);
        __nv_bfloat16* ph = buf + CH_AH + r * LDA + kq * 4;
        __nv_bfloat16* pl = buf + CH_AL + r * LDA + kq * 4;
        *(__nv_bfloat162*)ph       = __nv_bfloat162(hx, hy);
        *(__nv_bfloat162*)(ph + 2) = __nv_bfloat162(hz, hw);
        *(__nv_bfloat162*)pl       = __nv_bfloat162(
            __float2bfloat16_rn(v.x - __bfloat162float(hx)),
            __float2bfloat16_rn(v.y - __bfloat162float(hy)));
        *(__nv_bfloat162*)(pl + 2) = __nv_bfloat162(
            __float2bfloat16_rn(v.z - __bfloat162float(hz)),
            __float2bfloat16_rn(v.w - __bfloat162float(hw)));
    }
#pragma unroll
    for (int u = 0; u < 4; u++) {
        int idx = tid + u * 256;
        int r = idx >> 4, cq = idx & 15;
        *(uint4*)(buf + CH_BH + r * LDB + cq * 8) = P.bh[u];
        *(uint4*)(buf + CH_BL + r * LDB + cq * 8) = P.bl[u];
    }
}

__global__ void __launch_bounds__(256) gemm_wmma_kernel(const float* __restrict__ feat) {
    extern __shared__ __nv_bfloat16 sm[];
    __nv_bfloat16* buf0 = sm;
    __nv_bfloat16* buf1 = sm + CH_ELEM;
    int tid = threadIdx.x, wid = tid >> 5;
    int wy = wid & 3, wx = wid >> 2;              // 4 x 2 warp grid
    int row0 = blockIdx.x * BM, col0 = blockIdx.y * BN;

    wmma::fragment<wmma::accumulator, 16, 16, 16, float> acc[2][4];
#pragma unroll
    for (int i = 0; i < 2; i++)
#pragma unroll
        for (int j = 0; j < 4; j++) wmma::fill_fragment(acc[i][j], 0.f);

    Pref P;
    gemm_load(P, feat, row0, col0, 0, tid);
    gemm_store(P, buf0, tid);
    __syncthreads();

    for (int c = 0; c < 4; c++) {
        __nv_bfloat16* cur = (c & 1) ? buf1 : buf0;
        __nv_bfloat16* nxt = (c & 1) ? buf0 : buf1;
        if (c < 3) gemm_load(P, feat, row0, col0, c + 1, tid);   // LDG overlaps MMA

#pragma unroll
        for (int kk = 0; kk < 4; kk++) {
            wmma::fragment<wmma::matrix_a, 16, 16, 16, __nv_bfloat16, wmma::row_major> fa_h[2], fa_l[2];
            wmma::fragment<wmma::matrix_b, 16, 16, 16, __nv_bfloat16, wmma::row_major> fb_h[4], fb_l[4];
#pragma unroll
            for (int i = 0; i < 2; i++) {
                const __nv_bfloat16* p = cur + CH_AH + (wy * 32 + i * 16) * LDA + kk * 16;
                wmma::load_matrix_sync(fa_h[i], p, LDA);
                wmma::load_matrix_sync(fa_l[i], p + (CH_AL - CH_AH), LDA);
            }
#pragma unroll
            for (int j = 0; j < 4; j++) {
                const __nv_bfloat16* p = cur + CH_BH + (kk * 16) * LDB + wx * 64 + j * 16;
                wmma::load_matrix_sync(fb_h[j], p, LDB);
                wmma::load_matrix_sync(fb_l[j], p + (CH_BL - CH_BH), LDB);
            }
#pragma unroll
            for (int i = 0; i < 2; i++)
#pragma unroll
                for (int j = 0; j < 4; j++) {
                    wmma::mma_sync(acc[i][j], fa_h[i], fb_h[j], acc[i][j]);
                    wmma::mma_sync(acc[i][j], fa_h[i], fb_l[j], acc[i][j]);
                    wmma::mma_sync(acc[i][j], fa_l[i], fb_h[j], acc[i][j]);
                }
        }
        if (c < 3) gemm_store(P, nxt, tid);
        __syncthreads();
    }
    // store 32x64 per warp (g_h row-padded to NPAD, no guards needed)
#pragma unroll
    for (int i = 0; i < 2; i++)
#pragma unroll
        for (int j = 0; j < 4; j++) {
            float* p = g_h + (size_t)(row0 + wy * 32 + i * 16) * 256 + col0 + wx * 64 + j * 16;
            wmma::store_matrix_sync(p, acc[i][j], 256, wmma::mem_row_major);
        }
}

// per (node,head): el, er, a_l dot products. one warp per pair.
__global__ void dots_kernel(const float* __restrict__ attn_l,
                            const float* __restrict__ attn_r,
                            const float* __restrict__ hop_attn_l) {
    int pair = blockIdx.x * 8 + (threadIdx.x >> 5);
    if (pair >= NH) return;
    int lane = threadIdx.x & 31;
    int hd = pair & 3;
    float2 v = ((const float2*)(g_h + (size_t)pair * FF))[lane];
    float2 wl = ((const float2*)(attn_l + hd * FF))[lane];
    float2 wr = ((const float2*)(attn_r + hd * FF))[lane];
    float2 wh = ((const float2*)(hop_attn_l + hd * FF))[lane];
    float dl = warpAllReduce(v.x * wl.x + v.y * wl.y);
    float dr = warpAllReduce(v.x * wr.x + v.y * wr.y);
    float dh = warpAllReduce(v.x * wh.x + v.y * wh.y);
    if (lane == 0) { g_el[pair] = dl; g_er[pair] = dr; g_al[pair] = dh; }
}

// fused edge pass: logits + exp + both segment sums + degrees
__global__ void edgeAB_kernel(const int* __restrict__ src, const int* __restrict__ dst) {
    int t = blockIdx.x * blockDim.x + threadIdx.x;
    if (t >= EH) return;
    int e = t >> 2, hd = t & 3;
    int s = src[e], d = dst[e];
    float ev = leaky(g_el[s * HH + hd] + g_er[d * HH + hd]);
    g_e[t] = ev;
    float ex = __expf(ev);
    atomicAdd(&g_sum_src[s * HH + hd], ex);
    atomicAdd(&g_sum_dst[d * HH + hd], ex);
    if (hd == 0) { atomicAdd(&g_outdeg[s], 1); atomicAdd(&g_indeg[d], 1); }
}

// degree norms + log of softmax denominators (in-place)
__global__ void norm_kernel() {
    int i = blockIdx.x * blockDim.x + threadIdx.x;
    if (i < NN) {
        g_nout[i] = rsqrtf((float)max(g_outdeg[i], 1));
        g_nin[i]  = sqrtf((float)max(g_indeg[i], 1));
    }
    if (i < NH) {
        g_sum_src[i] = __logf(g_sum_src[i]);
        g_sum_dst[i] = __logf(g_sum_dst[i]);
    }
}

// ---- two-level exclusive scan of indeg -> off ----
__global__ void scanA_kernel() {
    int t = threadIdx.x, lane = t & 31, wid = t >> 5;
    int idx = blockIdx.x * 256 + t;
    int v = (idx < NN) ? g_indeg[idx] : 0;
    int x = v;
#pragma unroll
    for (int o = 1; o < 32; o <<= 1) {
        int y = __shfl_up_sync(0xffffffffu, x, o);
        if (lane >= o) x += y;
    }
    __shared__ int ws[8];
    if (lane == 31) ws[wid] = x;
    __syncthreads();
    if (t < 8) {
        int y = ws[t];
#pragma unroll
        for (int o = 1; o < 8; o <<= 1) {
            int z = __shfl_up_sync(0xffu, y, o);
            if (t >= o) y += z;
        }
        ws[t] = y;
    }
    __syncthreads();
    int incl = x + (wid ? ws[wid - 1] : 0);
    if (idx < NN) g_off[idx] = incl - v;
    if (t == 255) g_bsum[blockIdx.x] = incl;
}

__global__ void scanB_kernel(int nblk) {
    int t = threadIdx.x, lane = t & 31, wid = t >> 5;
    int v = (t < nblk) ? g_bsum[t] : 0;
    int x = v;
#pragma unroll
    for (int o = 1; o < 32; o <<= 1) {
        int y = __shfl_up_sync(0xffffffffu, x, o);
        if (lane >= o) x += y;
    }
    __shared__ int ws[8];
    if (lane == 31) ws[wid] = x;
    __syncthreads();
    if (t < 8) {
        int y = ws[t];
#pragma unroll
        for (int o = 1; o < 8; o <<= 1) {
            int z = __shfl_up_sync(0xffu, y, o);
            if (t >= o) y += z;
        }
        ws[t] = y;
    }
    __syncthreads();
    int incl = x + (wid ? ws[wid - 1] : 0);
    g_boff[t] = incl - v;
}

__global__ void scanC_kernel() {
    int idx = blockIdx.x * 256 + threadIdx.x;
    if (idx < NN) g_off[idx] += g_boff[blockIdx.x];
    if (idx == 0) g_off[NN] = EE;
}

__global__ void scatter_kernel(const int* __restrict__ src, const int* __restrict__ dst) {
    int e = blockIdx.x * blockDim.x + threadIdx.x;
    if (e >= EE) return;
    int d = dst[e];
    int pos = g_off[d] + atomicAdd(&g_cnt[d], 1);
    g_csr_src[pos] = src[e];
    g_pos[e] = pos;
}

// final coefficient, written directly in CSR order
__global__ void edgeC_kernel(const int* __restrict__ src, const int* __restrict__ dst,
                             const float* __restrict__ sigma) {
    int t = blockIdx.x * blockDim.x + threadIdx.x;
    if (t >= EH) return;
    float sg = 1.f / (1.f + __expf(-sigma[0]));
    int e = t >> 2, hd = t & 3;
    int s = src[e], d = dst[e];
    float ev = g_e[t];
    float ls = fmaxf(ev - g_sum_src[s * HH + hd], LCLIP);
    float ld = fmaxf(ev - g_sum_dst[d * HH + hd], LCLIP);
    g_c[g_pos[e] * HH + hd] = __expf((1.f - sg) * ls + sg * ld) * g_nout[s];
}

// one hop: xn[d,h,:] = nin[d] * sum_{e in in(d)} c[e,h] * x[src_e,h,:]
__global__ void prop_kernel(int hop) {
    const float* x;
    float* xn;
    if (hop == 0)      { x = g_h;  xn = g_x1; }
    else if (hop == 1) { x = g_x1; xn = g_x2; }
    else               { x = g_x2; xn = g_x3; }
    int pair = blockIdx.x * 8 + (threadIdx.x >> 5);
    if (pair >= NH) return;
    int lane = threadIdx.x & 31;
    int n = pair >> 2, hd = pair & 3;
    int beg = g_off[n], end = g_off[n + 1];
    float ax = 0.f, ay = 0.f;
    int p = beg;
    for (; p + 3 < end; p += 4) {
        int s0 = g_csr_src[p],     s1 = g_csr_src[p + 1];
        int s2 = g_csr_src[p + 2], s3 = g_csr_src[p + 3];
        float c0 = g_c[p * HH + hd],       c1 = g_c[(p + 1) * HH + hd];
        float c2 = g_c[(p + 2) * HH + hd], c3 = g_c[(p + 3) * HH + hd];
        float2 v0 = ((const float2*)(x + (size_t)(s0 * HH + hd) * FF))[lane];
        float2 v1 = ((const float2*)(x + (size_t)(s1 * HH + hd) * FF))[lane];
        float2 v2 = ((const float2*)(x + (size_t)(s2 * HH + hd) * FF))[lane];
        float2 v3 = ((const float2*)(x + (size_t)(s3 * HH + hd) * FF))[lane];
        ax += c0 * v0.x + c1 * v1.x + c2 * v2.x + c3 * v3.x;
        ay += c0 * v0.y + c1 * v1.y + c2 * v2.y + c3 * v3.y;
    }
    for (; p < end; p++) {
        int s0 = g_csr_src[p];
        float c0 = g_c[p * HH + hd];
        float2 v0 = ((const float2*)(x + (size_t)(s0 * HH + hd) * FF))[lane];
        ax += c0 * v0.x;
        ay += c0 * v0.y;
    }
    float ni = g_nin[n];
    ((float2*)(xn + (size_t)pair * FF))[lane] = make_float2(ax * ni, ay * ni);
}

// hop-attention combine -> output
__global__ void combine_kernel(const float* __restrict__ hop_attn_r,
                               float* __restrict__ out) {
    int pair = blockIdx.x * 8 + (threadIdx.x >> 5);
    if (pair >= NH) return;
    int lane = threadIdx.x & 31;
    int hd = pair & 3;
    float2 wr = ((const float2*)(hop_attn_r + hd * FF))[lane];
    float2 v0 = ((const float2*)(g_h  + (size_t)pair * FF))[lane];
    float2 v1 = ((const float2*)(g_x1 + (size_t)pair * FF))[lane];
    float2 v2 = ((const float2*)(g_x2 + (size_t)pair * FF))[lane];
    float2 v3 = ((const float2*)(g_x3 + (size_t)pair * FF))[lane];
    float d0 = warpAllReduce(v0.x * wr.x + v0.y * wr.y);
    float d1 = warpAllReduce(v1.x * wr.x + v1.y * wr.y);
    float d2 = warpAllReduce(v2.x * wr.x + v2.y * wr.y);
    float d3 = warpAllReduce(v3.x * wr.x + v3.y * wr.y);
    float al = g_al[pair];
    float b0 = leaky(al + d0), b1 = leaky(al + d1);
    float b2 = leaky(al + d2), b3 = leaky(al + d3);
    float m = fmaxf(fmaxf(b0, b1), fmaxf(b2, b3));
    float e0 = __expf(b0 - m), e1 = __expf(b1 - m);
    float e2 = __expf(b2 - m), e3 = __expf(b3 - m);
    float inv = 1.f / (e0 + e1 + e2 + e3);
    e0 *= inv; e1 *= inv; e2 *= inv; e3 *= inv;
    float2 r;
    r.x = v0.x * e0 + v1.x * e1 + v2.x * e2 + v3.x * e3;
    r.y = v0.y * e0 + v1.y * e1 + v2.y * e2 + v3.y * e3;
    ((float2*)(out + (size_t)pair * FF))[lane] = r;
}

// ---------------- launch ----------------------------------------------------
extern "C" void kernel_launch(void* const* d_in, const int* in_sizes, int n_in,
                              void* d_out, int out_size) {
    const float* feat  = (const float*)d_in[0];
    const int*   src   = (const int*)d_in[1];
    const int*   dst   = (const int*)d_in[2];
    const float* W     = (const float*)d_in[3];
    const float* attn_l     = (const float*)d_in[4];
    const float* attn_r     = (const float*)d_in[5];
    const float* hop_attn_l = (const float*)d_in[6];
    const float* hop_attn_r = (const float*)d_in[7];
    const float* sigma      = (const float*)d_in[8];
    float* out = (float*)d_out;

    const int NBLK = (NN + 255) / 256;   // 196

    cudaFuncSetAttribute(gemm_wmma_kernel,
                         cudaFuncAttributeMaxDynamicSharedMemorySize, GS_BYTES);

    init_kernel<<<(NH + 255) / 256, 256>>>();
    convertW_kernel<<<64, 256>>>(W);
    gemm_wmma_kernel<<<dim3(NPAD / BM, 2), 256, GS_BYTES>>>(feat);
    dots_kernel<<<(NH + 7) / 8, 256>>>(attn_l, attn_r, hop_attn_l);
    edgeAB_kernel<<<(EH + 255) / 256, 256>>>(src, dst);
    norm_kernel<<<(NH + 255) / 256, 256>>>();
    scanA_kernel<<<NBLK, 256>>>();
    scanB_kernel<<<1, 256>>>(NBLK);
    scanC_kernel<<<NBLK, 256>>>();
    scatter_kernel<<<(EE + 255) / 256, 256>>>(src, dst);
    edgeC_kernel<<<(EH + 255) / 256, 256>>>(src, dst, sigma);
    prop_kernel<<<(NH + 7) / 8, 256>>>(0);
    prop_kernel<<<(NH + 7) / 8, 256>>>(1);
    prop_kernel<<<(NH + 7) / 8, 256>>>(2);
    combine_kernel<<<(NH + 7) / 8, 256>>>(hop_attn_r, out);
}